// round 14
// baseline (speedup 1.0000x reference)
#include <cuda_runtime.h>
#include <cstdint>
#include <math.h>

#define T_LEN  2048
#define D_EMB  300
#define H_DIM  256
#define G4     1024
#define K_TAGS 48
#define START_TAG 46
#define STOP_TAG  47

// ---------------- scratch (device globals; no allocation) ----------------
__device__ float g_xg[2][T_LEN * G4];       // input projections per dir [T, 4H]
__device__ float g_hs[2][T_LEN * H_DIM];    // hidden states per dir, time-aligned
__device__ float g_feats[T_LEN * K_TAGS];   // emission features [T, K]
__device__ int   g_ready[2][32];            // xg tile ready count (16 = full)
__device__ int   g_feats_ready[32];         // feats 64-step tile ready flags

// ---------------- f32x2 helpers ----------------
__device__ __forceinline__ unsigned long long pack2(float lo, float hi) {
    unsigned long long r;
    asm("mov.b64 %0, {%1,%2};" : "=l"(r) : "f"(lo), "f"(hi));
    return r;
}
__device__ __forceinline__ void unpack2(unsigned long long v, float& lo, float& hi) {
    asm("mov.b64 {%0,%1}, %2;" : "=f"(lo), "=f"(hi) : "l"(v));
}
__device__ __forceinline__ unsigned long long mul2(unsigned long long a, unsigned long long b) {
    unsigned long long d;
    asm("mul.rn.f32x2 %0, %1, %2;" : "=l"(d) : "l"(a), "l"(b));
    return d;
}
__device__ __forceinline__ unsigned long long fma2(unsigned long long a, unsigned long long b,
                                                   unsigned long long c) {
    unsigned long long d;
    asm("fma.rn.f32x2 %0, %1, %2, %3;" : "=l"(d) : "l"(a), "l"(b), "l"(c));
    return d;
}
__device__ __forceinline__ int ld_acquire_gpu(const int* p) {
    int v;
    asm volatile("ld.acquire.gpu.s32 %0, [%1];" : "=r"(v) : "l"(p) : "memory");
    return v;
}

// ================= MEGA KERNEL 1: xg-GEMM workers + LSTM clusters =================
// grid (8, 18), cluster (8,1,1), 512 threads.
//  y < 2  : LSTM 8-CTA cluster for direction y (frozen champion protocol).
//  y >= 2 : 128 worker CTAs computing xg = gather(E,sent) @ W_ih^T + b_ih + b_hh
//           for BOTH dirs, t-tile-major so early timesteps complete first.
__global__ void __launch_bounds__(512, 1) __cluster_dims__(8, 1, 1)
mega_kernel(const int* __restrict__ sent, const float* __restrict__ E,
            const float* __restrict__ Wihf, const float* __restrict__ Whhf,
            const float* __restrict__ bihf, const float* __restrict__ bhhf,
            const float* __restrict__ Wihb, const float* __restrict__ Whhb,
            const float* __restrict__ bihb, const float* __restrict__ bhhb) {
    __shared__ float h_buf[2][H_DIM];
    __shared__ float As[12][64];
    __shared__ float Bs[12][64];

    int tid = threadIdx.x;

    if (blockIdx.y >= 2) {
        // ---------------- xg-GEMM worker role ----------------
        int worker = (int)(blockIdx.y - 2) * 8 + (int)blockIdx.x;   // 0..127
#pragma unroll 1
        for (int pass = 0; pass < 8; pass++) {
            int tile = worker + pass * 128;      // 0..1023, t-tile-major
            int ttile = tile >> 5;
            int rem = tile & 31;
            int rtile = rem >> 1;
            int dir = rem & 1;
            int t0 = ttile * 64;
            int r0 = rtile * 64;
            const float* Wih = dir ? Wihb : Wihf;
            const float* b1 = dir ? bihb : bihf;
            const float* b2 = dir ? bhhb : bhhf;

            int tx = tid & 15;       // 4 output cols
            int ty = tid >> 4;       // 32 groups of 2 output rows (time)
            float acc[2][4];
#pragma unroll
            for (int i = 0; i < 2; i++)
#pragma unroll
                for (int j = 0; j < 4; j++) acc[i][j] = 0.f;

            for (int k0 = 0; k0 < D_EMB; k0 += 12) {
#pragma unroll
                for (int l2 = 0; l2 < 2; l2++) {
                    int idx = tid + l2 * 512;
                    if (idx < 768) {
                        int row = idx / 12;
                        int kk = idx - row * 12;
                        int tg = t0 + row;
                        int ts = dir ? (T_LEN - 1 - tg) : tg;
                        long long vrow = sent[ts];
                        As[kk][row] = E[vrow * D_EMB + k0 + kk];
                        Bs[kk][row] = Wih[(size_t)(r0 + row) * D_EMB + k0 + kk];
                    }
                }
                __syncthreads();
#pragma unroll
                for (int kk = 0; kk < 12; kk++) {
                    float ra0 = As[kk][ty * 2];
                    float ra1 = As[kk][ty * 2 + 1];
                    float rb[4];
#pragma unroll
                    for (int j = 0; j < 4; j++) rb[j] = Bs[kk][tx * 4 + j];
#pragma unroll
                    for (int j = 0; j < 4; j++) {
                        acc[0][j] += ra0 * rb[j];
                        acc[1][j] += ra1 * rb[j];
                    }
                }
                __syncthreads();
            }

#pragma unroll
            for (int i = 0; i < 2; i++) {
                int t = t0 + ty * 2 + i;
#pragma unroll
                for (int j = 0; j < 4; j++) {
                    int r = r0 + tx * 4 + j;
                    g_xg[dir][(size_t)t * G4 + r] = acc[i][j] + b1[r] + b2[r];
                }
            }
            __syncthreads();
            __threadfence();
            if (tid == 0) atomicAdd(&g_ready[dir][ttile], 1);
        }
        return;
    }

    // ---------------- LSTM cluster role (frozen champion) ----------------
    int dir = blockIdx.y;
    const float* Whh = dir ? Whhb : Whhf;
    const float* xg = g_xg[dir];
    float* hs = g_hs[dir];

    uint32_t rank;
    asm("mov.u32 %0, %%cluster_ctarank;" : "=r"(rank));

    int w = tid >> 5;
    int l = tid & 31;
    int r = (l >> 2) & 7;          // W row this lane finalizes (lane bits 4,3,2)
    int gate = r & 3;
    int du = r >> 2;               // which of the warp's 2 units (== l>>4)
    int xg_col = gate * H_DIM + (int)rank * 32 + 2 * w + du;

    unsigned long long w2[8][4];
#pragma unroll
    for (int q = 0; q < 8; q++) {
        int row = (q & 3) * H_DIM + (int)rank * 32 + 2 * w + (q >> 2);
        const float4* p = (const float4*)(Whh + (size_t)row * H_DIM + l * 8);
        float4 a = p[0];
        float4 b = p[1];
        w2[q][0] = pack2(a.x, a.y); w2[q][1] = pack2(a.z, a.w);
        w2[q][2] = pack2(b.x, b.y); w2[q][3] = pack2(b.z, b.w);
    }

    if (tid < 2 * H_DIM) ((float*)h_buf)[tid] = 0.f;
    uint32_t hb = (uint32_t)__cvta_generic_to_shared(&h_buf[0][0]);

    uint32_t rH[8];
#pragma unroll
    for (int tg = 0; tg < 8; tg++) {
        asm("mapa.shared::cluster.u32 %0, %1, %2;" : "=r"(rH[tg]) : "r"(hb), "r"(tg));
    }

    __syncthreads();
    asm volatile("barrier.cluster.arrive.aligned;" ::: "memory");
    asm volatile("barrier.cluster.wait.aligned;" ::: "memory");

    // wait for xg tile 0 of this direction
    if (tid == 0) {
        while (ld_acquire_gpu(&g_ready[dir][0]) < 16) {}
    }
    __syncthreads();

    float c_reg = 0.f;
    float xg_pref = xg[xg_col];    // xg for t=0
    const float LOG2E = 1.4426950408889634f;
    const float act_a = (gate == 2) ? (2.f * LOG2E) : (-LOG2E);
    const bool  is_tanh = (gate == 2);

#pragma unroll 1
    for (int t = 0; t < T_LEN; t++) {
        int cur = t & 1;
        int nxt = cur ^ 1;

        // prefetch of xg[t+1] during this step crosses into tile (t+1)>>6
        if ((t & 63) == 63 && t + 1 < T_LEN) {
            if (tid == 0) {
                int need = (t + 1) >> 6;
                while (ld_acquire_gpu(&g_ready[dir][need]) < 16) {}
            }
            __syncthreads();
        }

        float4 ha = *(const float4*)&h_buf[cur][l * 8];
        float4 hc = *(const float4*)&h_buf[cur][l * 8 + 4];
        unsigned long long h2[4] = { pack2(ha.x, ha.y), pack2(ha.z, ha.w),
                                     pack2(hc.x, hc.y), pack2(hc.z, hc.w) };
        float v[8];
#pragma unroll
        for (int q = 0; q < 8; q++) {
            unsigned long long acc = mul2(w2[q][0], h2[0]);
            acc = fma2(w2[q][1], h2[1], acc);
            acc = fma2(w2[q][2], h2[2], acc);
            acc = fma2(w2[q][3], h2[3], acc);
            float lo, hi;
            unpack2(acc, lo, hi);
            v[q] = lo + hi;
        }

        // reduce-scatter onto lane bits 4,3,2 (row = (l>>2)&7)
#pragma unroll
        for (int i = 0; i < 4; i++) {
            float send = (l & 16) ? v[i] : v[i + 4];
            float recv = __shfl_xor_sync(0xffffffffu, send, 16);
            float keep = (l & 16) ? v[i + 4] : v[i];
            v[i] = keep + recv;
        }
#pragma unroll
        for (int i = 0; i < 2; i++) {
            float send = (l & 8) ? v[i] : v[i + 2];
            float recv = __shfl_xor_sync(0xffffffffu, send, 8);
            float keep = (l & 8) ? v[i + 2] : v[i];
            v[i] = keep + recv;
        }
        {
            float send = (l & 4) ? v[0] : v[1];
            float recv = __shfl_xor_sync(0xffffffffu, send, 4);
            float keep = (l & 4) ? v[1] : v[0];
            v[0] = keep + recv;
        }
        // combine the 4 partials living at lane bits 1,0
        float x = v[0];
        x += __shfl_xor_sync(0xffffffffu, x, 1);
        x += __shfl_xor_sync(0xffffffffu, x, 2);

        float pre = x + xg_pref;

        // branch-free activation: gate 2 -> tanh, else sigmoid (EX2 + RCP)
        float e = exp2f(act_a * pre);
        float z = __fdividef(1.f, 1.f + e);
        float act = is_tanh ? fmaf(-2.f, z, 1.f) : z;

        // gather i,f,g,o for this lane's unit du: rows du*4+g at lanes 16du+4g
        int gbase = du << 4;
        float iv = __shfl_sync(0xffffffffu, act, gbase);
        float fv = __shfl_sync(0xffffffffu, act, gbase + 4);
        float gg = __shfl_sync(0xffffffffu, act, gbase + 8);
        float ov = __shfl_sync(0xffffffffu, act, gbase + 12);

        c_reg = fmaf(fv, c_reg, iv * gg);
        float e2 = exp2f(2.f * LOG2E * c_reg);
        float hval = ov * fmaf(-2.f, __fdividef(1.f, 1.f + e2), 1.f);
        // hval identical within each du half (lanes 0-15: unit 2w; 16-31: 2w+1)

        // single xor-16: every lane obtains the other unit's h
        float h_other = __shfl_xor_sync(0xffffffffu, hval, 16);

        uint32_t off = (uint32_t)((nxt * H_DIM + (int)rank * 32 + 2 * w) * 4);
        if (l < 8) {   // lanes 0-7: du=0 -> hval=h0, h_other=h1
            unsigned long long pk = pack2(hval, h_other);
            asm volatile("st.shared::cluster.b64 [%0], %1;"
                         :: "r"(rH[l] + off), "l"(pk) : "memory");
        }

        asm volatile("barrier.cluster.arrive.aligned;" ::: "memory");

        // issue next-step xg load inside the barrier window (latency hidden)
        if (t + 1 < T_LEN)
            xg_pref = xg[(size_t)(t + 1) * G4 + xg_col];

        if (l == 8) {  // du=0: hval=h0, h_other=h1
            int tout = dir ? (T_LEN - 1 - t) : t;
            *(float2*)&hs[(size_t)tout * H_DIM + rank * 32 + 2 * w] =
                make_float2(hval, h_other);
        }

        asm volatile("barrier.cluster.wait.aligned;" ::: "memory");
    }

    asm volatile("barrier.cluster.arrive.aligned;" ::: "memory");
    asm volatile("barrier.cluster.wait.aligned;" ::: "memory");

    // reset this dir's ready counters for the next graph replay
    if (rank == 0 && tid < 32) g_ready[dir][tid] = 0;
}

// ================= MEGA KERNEL 2: feats GEMM workers + single-warp Viterbi =================
// grid 33 CTAs x 256 threads. CTAs 0..31: one 64-timestep feats tile each,
// publish g_feats_ready[tile]=1. CTA 32: Viterbi on WARP 0 ONLY (warps 1-7
// exit immediately; no block sync anywhere on CTA 32's path). Lane l owns tag
// l; lanes 0-15 additionally own tag 32+l (both transition rows in regs).
// Each lane scans all 48 prev-tags itself: 12 x LDS.128 broadcast of fv ->
// 4-ILP strict-> chains + first-index merge -> direct STS. Sync = __syncwarp.
#define FT_TT 64
#define VIT_SMEM (T_LEN * K_TAGS + 2 * K_TAGS * 4 + 16)
extern __shared__ unsigned char dyn_smem[];
__global__ void __launch_bounds__(256, 1)
feats_viterbi_kernel(const float* __restrict__ W_out,
                     const float* __restrict__ b_out,
                     const float* __restrict__ trans,
                     float* __restrict__ out) {
    int tid = threadIdx.x;

    if (blockIdx.x < 32) {
        // ---------------- feats tile role ----------------
        float (*As)[FT_TT]  = (float (*)[FT_TT])dyn_smem;               // [32][64]
        float (*Bs)[K_TAGS] = (float (*)[K_TAGS])(dyn_smem + 32 * FT_TT * 4);

        int t0 = (int)blockIdx.x * FT_TT;
        int tx = tid & 15;                // k-group: 3 tags
        int ty = tid >> 4;                // t-group: 4 steps

        float acc[4][3];
#pragma unroll
        for (int i = 0; i < 4; i++)
#pragma unroll
            for (int k = 0; k < 3; k++) acc[i][k] = 0.f;

        for (int j0 = 0; j0 < 2 * H_DIM; j0 += 32) {
#pragma unroll
            for (int i = 0; i < 8; i++) {
                int idx = tid + i * 256;        // 0..2047
                int jj = idx & 31;
                int tt = idx >> 5;
                int j = j0 + jj;
                float hv = (j < H_DIM)
                    ? g_hs[0][(size_t)(t0 + tt) * H_DIM + j]
                    : g_hs[1][(size_t)(t0 + tt) * H_DIM + (j - H_DIM)];
                As[jj][tt] = hv;
            }
#pragma unroll
            for (int i = 0; i < 6; i++) {
                int idx = tid + i * 256;        // 0..1535 = 32 j x 48 k
                int jj = idx & 31;
                int k = idx >> 5;               // 0..47
                Bs[jj][k] = W_out[(size_t)k * (2 * H_DIM) + j0 + jj];
            }
            __syncthreads();
#pragma unroll
            for (int jj = 0; jj < 32; jj++) {
                float a[4], b[3];
#pragma unroll
                for (int i = 0; i < 4; i++) a[i] = As[jj][ty * 4 + i];
#pragma unroll
                for (int k = 0; k < 3; k++) b[k] = Bs[jj][tx * 3 + k];
#pragma unroll
                for (int i = 0; i < 4; i++)
#pragma unroll
                    for (int k = 0; k < 3; k++) acc[i][k] += a[i] * b[k];
            }
            __syncthreads();
        }

#pragma unroll
        for (int i = 0; i < 4; i++) {
            int t = t0 + ty * 4 + i;
#pragma unroll
            for (int k = 0; k < 3; k++) {
                int kk = tx * 3 + k;
                g_feats[t * K_TAGS + kk] = acc[i][k] + b_out[kk];
            }
        }
        __syncthreads();
        __threadfence();
        if (tid == 0) atomicExch(&g_feats_ready[blockIdx.x], 1);
        return;
    }

    // ---------------- Viterbi role: warp 0 only ----------------
    if (tid >= 32) return;   // warps 1-7 exit (no block sync on this path)

    unsigned char* bptr = dyn_smem;                          // [T][48] u8 = 96KB
    float* fvs = (float*)(dyn_smem + T_LEN * K_TAGS);        // [2][48], 16B aligned
    int l = tid;
    int tagA = l;                      // 0..31
    int tagB = 32 + (l & 15);          // 32..47 (lanes 16-31 compute duplicates)
    bool ownB = (l < 16);

    float trA[48], trB[48];
#pragma unroll
    for (int j = 0; j < 48; j++) {
        trA[j] = trans[tagA * K_TAGS + j];
        trB[j] = trans[tagB * K_TAGS + j];
    }
    fvs[tagA] = (tagA == START_TAG) ? 0.f : -10000.f;
    if (ownB) fvs[tagB] = (tagB == START_TAG) ? 0.f : -10000.f;

    // wait for feats tile 0, then prefetch featp(t=0)
    if (l == 0) {
        while (ld_acquire_gpu(&g_feats_ready[0]) == 0) {}
    }
    __syncwarp();
    float featA = g_feats[tagA];
    float featB = g_feats[tagB];

#pragma unroll 1
    for (int t = 0; t < T_LEN; t++) {
        int cur = (t & 1) * K_TAGS;
        int nxt = K_TAGS - cur;

        const float4* fp = (const float4*)&fvs[cur];

        // 4-ILP strict-> chains over 48 prevs, both tags interleaved
        float bA0 = -3.4e38f, bA1 = -3.4e38f, bA2 = -3.4e38f, bA3 = -3.4e38f;
        int   aA0 = 0, aA1 = 1, aA2 = 2, aA3 = 3;
        float bB0 = -3.4e38f, bB1 = -3.4e38f, bB2 = -3.4e38f, bB3 = -3.4e38f;
        int   aB0 = 0, aB1 = 1, aB2 = 2, aB3 = 3;
#pragma unroll
        for (int q = 0; q < 12; q++) {
            float4 f = fp[q];               // fv[cur + 4q .. 4q+3] (broadcast)
            int j = q * 4;
            float sA0 = f.x + trA[j],     sB0 = f.x + trB[j];
            float sA1 = f.y + trA[j + 1], sB1 = f.y + trB[j + 1];
            float sA2 = f.z + trA[j + 2], sB2 = f.z + trB[j + 2];
            float sA3 = f.w + trA[j + 3], sB3 = f.w + trB[j + 3];
            if (sA0 > bA0) { bA0 = sA0; aA0 = j; }
            if (sA1 > bA1) { bA1 = sA1; aA1 = j + 1; }
            if (sA2 > bA2) { bA2 = sA2; aA2 = j + 2; }
            if (sA3 > bA3) { bA3 = sA3; aA3 = j + 3; }
            if (sB0 > bB0) { bB0 = sB0; aB0 = j; }
            if (sB1 > bB1) { bB1 = sB1; aB1 = j + 1; }
            if (sB2 > bB2) { bB2 = sB2; aB2 = j + 2; }
            if (sB3 > bB3) { bB3 = sB3; aB3 = j + 3; }
        }
        // combine with first-index tie-break (= jnp.argmax)
        float bvA = bA0; int baA = aA0;
        if (bA1 > bvA || (bA1 == bvA && aA1 < baA)) { bvA = bA1; baA = aA1; }
        if (bA2 > bvA || (bA2 == bvA && aA2 < baA)) { bvA = bA2; baA = aA2; }
        if (bA3 > bvA || (bA3 == bvA && aA3 < baA)) { bvA = bA3; baA = aA3; }
        float bvB = bB0; int baB = aB0;
        if (bB1 > bvB || (bB1 == bvB && aB1 < baB)) { bvB = bB1; baB = aB1; }
        if (bB2 > bvB || (bB2 == bvB && aB2 < baB)) { bvB = bB2; baB = aB2; }
        if (bB3 > bvB || (bB3 == bvB && aB3 < baB)) { bvB = bB3; baB = aB3; }

        fvs[nxt + tagA] = bvA + featA;
        bptr[t * K_TAGS + tagA] = (unsigned char)baA;
        if (ownB) {
            fvs[nxt + tagB] = bvB + featB;
            bptr[t * K_TAGS + tagB] = (unsigned char)baB;
        }

        if (t + 1 < T_LEN) {
            if ((t & 63) == 63) {          // crossing into a new feats tile
                if (l == 0) {
                    int need = (t + 1) >> 6;
                    while (ld_acquire_gpu(&g_feats_ready[need]) == 0) {}
                }
            }
            __syncwarp();
            featA = g_feats[(t + 1) * K_TAGS + tagA];
            featB = g_feats[(t + 1) * K_TAGS + tagB];
        } else {
            __syncwarp();
        }
    }

    if (l == 0) {
        int cur = (T_LEN & 1) * K_TAGS;   // = 0 for even T
        float best = -3.4e38f;
        int btag = 0;
#pragma unroll
        for (int j = 0; j < K_TAGS; j++) {
            float s = fvs[cur + j] + trans[STOP_TAG * K_TAGS + j];
            if (s > best) { best = s; btag = j; }
        }
        out[0] = best;
        for (int t = T_LEN - 1; t >= 0; t--) {
            out[1 + t] = (float)btag;
            btag = bptr[t * K_TAGS + btag];
        }
    }
    // reset feats flags for next graph replay (all were observed == 1)
    g_feats_ready[l] = 0;
}

// ---------------- launch ----------------
extern "C" void kernel_launch(void* const* d_in, const int* in_sizes, int n_in,
                              void* d_out, int out_size) {
    const int*   sent   = (const int*)d_in[0];
    const float* E      = (const float*)d_in[1];
    const float* W_ih_f = (const float*)d_in[2];
    const float* W_hh_f = (const float*)d_in[3];
    const float* b_ih_f = (const float*)d_in[4];
    const float* b_hh_f = (const float*)d_in[5];
    const float* W_ih_b = (const float*)d_in[6];
    const float* W_hh_b = (const float*)d_in[7];
    const float* b_ih_b = (const float*)d_in[8];
    const float* b_hh_b = (const float*)d_in[9];
    const float* W_out  = (const float*)d_in[10];
    const float* b_out  = (const float*)d_in[11];
    const float* trans  = (const float*)d_in[12];
    float* out = (float*)d_out;

    cudaFuncSetAttribute(feats_viterbi_kernel,
                         cudaFuncAttributeMaxDynamicSharedMemorySize, VIT_SMEM);

    // gather + xg GEMM + both LSTM directions in ONE launch
    mega_kernel<<<dim3(8, 18, 1), 512>>>(sent, E,
                                         W_ih_f, W_hh_f, b_ih_f, b_hh_f,
                                         W_ih_b, W_hh_b, b_ih_b, b_hh_b);

    // feats GEMM (CTAs 0-31) + single-warp Viterbi (CTA 32) in ONE launch
    feats_viterbi_kernel<<<33, 256, VIT_SMEM>>>(W_out, b_out, trans, out);
}

// round 15
// speedup vs baseline: 1.1815x; 1.1815x over previous
#include <cuda_runtime.h>
#include <cstdint>
#include <math.h>

#define T_LEN  2048
#define D_EMB  300
#define H_DIM  256
#define G4     1024
#define K_TAGS 48
#define START_TAG 46
#define STOP_TAG  47

// ---------------- scratch (device globals; no allocation) ----------------
__device__ float g_xg[2][T_LEN * G4];       // input projections per dir [T, 4H]
__device__ float g_hs[2][T_LEN * H_DIM];    // hidden states per dir, time-aligned
__device__ float g_feats[T_LEN * K_TAGS];   // emission features [T, K]
__device__ int   g_ready[2][32];            // xg tile ready count (16 = full)

// ---------------- f32x2 helpers ----------------
__device__ __forceinline__ unsigned long long pack2(float lo, float hi) {
    unsigned long long r;
    asm("mov.b64 %0, {%1,%2};" : "=l"(r) : "f"(lo), "f"(hi));
    return r;
}
__device__ __forceinline__ void unpack2(unsigned long long v, float& lo, float& hi) {
    asm("mov.b64 {%0,%1}, %2;" : "=f"(lo), "=f"(hi) : "l"(v));
}
__device__ __forceinline__ unsigned long long mul2(unsigned long long a, unsigned long long b) {
    unsigned long long d;
    asm("mul.rn.f32x2 %0, %1, %2;" : "=l"(d) : "l"(a), "l"(b));
    return d;
}
__device__ __forceinline__ unsigned long long fma2(unsigned long long a, unsigned long long b,
                                                   unsigned long long c) {
    unsigned long long d;
    asm("fma.rn.f32x2 %0, %1, %2, %3;" : "=l"(d) : "l"(a), "l"(b), "l"(c));
    return d;
}
__device__ __forceinline__ int ld_acquire_gpu(const int* p) {
    int v;
    asm volatile("ld.acquire.gpu.s32 %0, [%1];" : "=r"(v) : "l"(p) : "memory");
    return v;
}

// ================= MEGA KERNEL: xg-GEMM workers + LSTM clusters =================
// grid (8, 18), cluster (8,1,1), 512 threads.
//  y < 2  : LSTM 8-CTA cluster for direction y (frozen champion protocol).
//  y >= 2 : 128 worker CTAs computing xg = gather(E,sent) @ W_ih^T + b_ih + b_hh
//           for BOTH dirs, t-tile-major so early timesteps complete first.
__global__ void __launch_bounds__(512, 1) __cluster_dims__(8, 1, 1)
mega_kernel(const int* __restrict__ sent, const float* __restrict__ E,
            const float* __restrict__ Wihf, const float* __restrict__ Whhf,
            const float* __restrict__ bihf, const float* __restrict__ bhhf,
            const float* __restrict__ Wihb, const float* __restrict__ Whhb,
            const float* __restrict__ bihb, const float* __restrict__ bhhb) {
    __shared__ float h_buf[2][H_DIM];
    __shared__ float As[12][64];
    __shared__ float Bs[12][64];

    int tid = threadIdx.x;

    if (blockIdx.y >= 2) {
        // ---------------- xg-GEMM worker role ----------------
        int worker = (int)(blockIdx.y - 2) * 8 + (int)blockIdx.x;   // 0..127
#pragma unroll 1
        for (int pass = 0; pass < 8; pass++) {
            int tile = worker + pass * 128;      // 0..1023, t-tile-major
            int ttile = tile >> 5;
            int rem = tile & 31;
            int rtile = rem >> 1;
            int dir = rem & 1;
            int t0 = ttile * 64;
            int r0 = rtile * 64;
            const float* Wih = dir ? Wihb : Wihf;
            const float* b1 = dir ? bihb : bihf;
            const float* b2 = dir ? bhhb : bhhf;

            int tx = tid & 15;       // 4 output cols
            int ty = tid >> 4;       // 32 groups of 2 output rows (time)
            float acc[2][4];
#pragma unroll
            for (int i = 0; i < 2; i++)
#pragma unroll
                for (int j = 0; j < 4; j++) acc[i][j] = 0.f;

            for (int k0 = 0; k0 < D_EMB; k0 += 12) {
#pragma unroll
                for (int l2 = 0; l2 < 2; l2++) {
                    int idx = tid + l2 * 512;
                    if (idx < 768) {
                        int row = idx / 12;
                        int kk = idx - row * 12;
                        int tg = t0 + row;
                        int ts = dir ? (T_LEN - 1 - tg) : tg;
                        long long vrow = sent[ts];
                        As[kk][row] = E[vrow * D_EMB + k0 + kk];
                        Bs[kk][row] = Wih[(size_t)(r0 + row) * D_EMB + k0 + kk];
                    }
                }
                __syncthreads();
#pragma unroll
                for (int kk = 0; kk < 12; kk++) {
                    float ra0 = As[kk][ty * 2];
                    float ra1 = As[kk][ty * 2 + 1];
                    float rb[4];
#pragma unroll
                    for (int j = 0; j < 4; j++) rb[j] = Bs[kk][tx * 4 + j];
#pragma unroll
                    for (int j = 0; j < 4; j++) {
                        acc[0][j] += ra0 * rb[j];
                        acc[1][j] += ra1 * rb[j];
                    }
                }
                __syncthreads();
            }

#pragma unroll
            for (int i = 0; i < 2; i++) {
                int t = t0 + ty * 2 + i;
#pragma unroll
                for (int j = 0; j < 4; j++) {
                    int r = r0 + tx * 4 + j;
                    g_xg[dir][(size_t)t * G4 + r] = acc[i][j] + b1[r] + b2[r];
                }
            }
            __syncthreads();
            __threadfence();
            if (tid == 0) atomicAdd(&g_ready[dir][ttile], 1);
        }
        return;
    }

    // ---------------- LSTM cluster role (frozen champion) ----------------
    int dir = blockIdx.y;
    const float* Whh = dir ? Whhb : Whhf;
    const float* xg = g_xg[dir];
    float* hs = g_hs[dir];

    uint32_t rank;
    asm("mov.u32 %0, %%cluster_ctarank;" : "=r"(rank));

    int w = tid >> 5;
    int l = tid & 31;
    int r = (l >> 2) & 7;          // W row this lane finalizes (lane bits 4,3,2)
    int gate = r & 3;
    int du = r >> 2;               // which of the warp's 2 units (== l>>4)
    int xg_col = gate * H_DIM + (int)rank * 32 + 2 * w + du;

    unsigned long long w2[8][4];
#pragma unroll
    for (int q = 0; q < 8; q++) {
        int row = (q & 3) * H_DIM + (int)rank * 32 + 2 * w + (q >> 2);
        const float4* p = (const float4*)(Whh + (size_t)row * H_DIM + l * 8);
        float4 a = p[0];
        float4 b = p[1];
        w2[q][0] = pack2(a.x, a.y); w2[q][1] = pack2(a.z, a.w);
        w2[q][2] = pack2(b.x, b.y); w2[q][3] = pack2(b.z, b.w);
    }

    if (tid < 2 * H_DIM) ((float*)h_buf)[tid] = 0.f;
    uint32_t hb = (uint32_t)__cvta_generic_to_shared(&h_buf[0][0]);

    uint32_t rH[8];
#pragma unroll
    for (int tg = 0; tg < 8; tg++) {
        asm("mapa.shared::cluster.u32 %0, %1, %2;" : "=r"(rH[tg]) : "r"(hb), "r"(tg));
    }

    __syncthreads();
    asm volatile("barrier.cluster.arrive.aligned;" ::: "memory");
    asm volatile("barrier.cluster.wait.aligned;" ::: "memory");

    // wait for xg tile 0 of this direction
    if (tid == 0) {
        while (ld_acquire_gpu(&g_ready[dir][0]) < 16) {}
    }
    __syncthreads();

    float c_reg = 0.f;
    float xg_pref = xg[xg_col];    // xg for t=0
    const float LOG2E = 1.4426950408889634f;
    const float act_a = (gate == 2) ? (2.f * LOG2E) : (-LOG2E);
    const bool  is_tanh = (gate == 2);

#pragma unroll 1
    for (int t = 0; t < T_LEN; t++) {
        int cur = t & 1;
        int nxt = cur ^ 1;

        // prefetch of xg[t+1] during this step crosses into tile (t+1)>>6
        if ((t & 63) == 63 && t + 1 < T_LEN) {
            if (tid == 0) {
                int need = (t + 1) >> 6;
                while (ld_acquire_gpu(&g_ready[dir][need]) < 16) {}
            }
            __syncthreads();
        }

        float4 ha = *(const float4*)&h_buf[cur][l * 8];
        float4 hc = *(const float4*)&h_buf[cur][l * 8 + 4];
        unsigned long long h2[4] = { pack2(ha.x, ha.y), pack2(ha.z, ha.w),
                                     pack2(hc.x, hc.y), pack2(hc.z, hc.w) };
        float v[8];
#pragma unroll
        for (int q = 0; q < 8; q++) {
            unsigned long long acc = mul2(w2[q][0], h2[0]);
            acc = fma2(w2[q][1], h2[1], acc);
            acc = fma2(w2[q][2], h2[2], acc);
            acc = fma2(w2[q][3], h2[3], acc);
            float lo, hi;
            unpack2(acc, lo, hi);
            v[q] = lo + hi;
        }

        // reduce-scatter onto lane bits 4,3,2 (row = (l>>2)&7)
#pragma unroll
        for (int i = 0; i < 4; i++) {
            float send = (l & 16) ? v[i] : v[i + 4];
            float recv = __shfl_xor_sync(0xffffffffu, send, 16);
            float keep = (l & 16) ? v[i + 4] : v[i];
            v[i] = keep + recv;
        }
#pragma unroll
        for (int i = 0; i < 2; i++) {
            float send = (l & 8) ? v[i] : v[i + 2];
            float recv = __shfl_xor_sync(0xffffffffu, send, 8);
            float keep = (l & 8) ? v[i + 2] : v[i];
            v[i] = keep + recv;
        }
        {
            float send = (l & 4) ? v[0] : v[1];
            float recv = __shfl_xor_sync(0xffffffffu, send, 4);
            float keep = (l & 4) ? v[1] : v[0];
            v[0] = keep + recv;
        }
        // combine the 4 partials living at lane bits 1,0
        float x = v[0];
        x += __shfl_xor_sync(0xffffffffu, x, 1);
        x += __shfl_xor_sync(0xffffffffu, x, 2);

        float pre = x + xg_pref;

        // branch-free activation: gate 2 -> tanh, else sigmoid (EX2 + RCP)
        float e = exp2f(act_a * pre);
        float z = __fdividef(1.f, 1.f + e);
        float act = is_tanh ? fmaf(-2.f, z, 1.f) : z;

        // gather i,f,g,o for this lane's unit du: rows du*4+g at lanes 16du+4g
        int gbase = du << 4;
        float iv = __shfl_sync(0xffffffffu, act, gbase);
        float fv = __shfl_sync(0xffffffffu, act, gbase + 4);
        float gg = __shfl_sync(0xffffffffu, act, gbase + 8);
        float ov = __shfl_sync(0xffffffffu, act, gbase + 12);

        c_reg = fmaf(fv, c_reg, iv * gg);
        float e2 = exp2f(2.f * LOG2E * c_reg);
        float hval = ov * fmaf(-2.f, __fdividef(1.f, 1.f + e2), 1.f);
        // hval identical within each du half (lanes 0-15: unit 2w; 16-31: 2w+1)

        // single xor-16: every lane obtains the other unit's h
        float h_other = __shfl_xor_sync(0xffffffffu, hval, 16);

        uint32_t off = (uint32_t)((nxt * H_DIM + (int)rank * 32 + 2 * w) * 4);
        if (l < 8) {   // lanes 0-7: du=0 -> hval=h0, h_other=h1
            unsigned long long pk = pack2(hval, h_other);
            asm volatile("st.shared::cluster.b64 [%0], %1;"
                         :: "r"(rH[l] + off), "l"(pk) : "memory");
        }

        asm volatile("barrier.cluster.arrive.aligned;" ::: "memory");

        // issue next-step xg load inside the barrier window (latency hidden)
        if (t + 1 < T_LEN)
            xg_pref = xg[(size_t)(t + 1) * G4 + xg_col];

        if (l == 8) {  // du=0: hval=h0, h_other=h1
            int tout = dir ? (T_LEN - 1 - t) : t;
            *(float2*)&hs[(size_t)tout * H_DIM + rank * 32 + 2 * w] =
                make_float2(hval, h_other);
        }

        asm volatile("barrier.cluster.wait.aligned;" ::: "memory");
    }

    asm volatile("barrier.cluster.arrive.aligned;" ::: "memory");
    asm volatile("barrier.cluster.wait.aligned;" ::: "memory");

    // reset this dir's ready counters for the next graph replay
    if (rank == 0 && tid < 32) g_ready[dir][tid] = 0;
}

// ---------------- feats GEMM: [T,512] @ [48,512]^T + b_out ----------------
#define FT_TT 64
__global__ void feats_gemm_kernel(const float* __restrict__ W_out,
                                  const float* __restrict__ b_out) {
    __shared__ float As[32][FT_TT];   // [j][t]
    __shared__ float Bs[32][K_TAGS];  // [j][k]

    int t0 = blockIdx.x * FT_TT;
    int tid = threadIdx.x;            // 256
    int tx = tid & 15;                // k-group: 3 tags
    int ty = tid >> 4;                // t-group: 4 steps

    float acc[4][3];
#pragma unroll
    for (int i = 0; i < 4; i++)
#pragma unroll
        for (int k = 0; k < 3; k++) acc[i][k] = 0.f;

    for (int j0 = 0; j0 < 2 * H_DIM; j0 += 32) {
#pragma unroll
        for (int i = 0; i < 8; i++) {
            int idx = tid + i * 256;        // 0..2047
            int jj = idx & 31;
            int tt = idx >> 5;
            int j = j0 + jj;
            float hv = (j < H_DIM)
                ? g_hs[0][(size_t)(t0 + tt) * H_DIM + j]
                : g_hs[1][(size_t)(t0 + tt) * H_DIM + (j - H_DIM)];
            As[jj][tt] = hv;
        }
        // coalesced W_out load: consecutive threads read consecutive j
#pragma unroll
        for (int i = 0; i < 6; i++) {
            int idx = tid + i * 256;        // 0..1535 = 32 j x 48 k
            int jj = idx & 31;
            int k = idx >> 5;               // 0..47
            Bs[jj][k] = W_out[(size_t)k * (2 * H_DIM) + j0 + jj];
        }
        __syncthreads();
#pragma unroll
        for (int jj = 0; jj < 32; jj++) {
            float a[4], b[3];
#pragma unroll
            for (int i = 0; i < 4; i++) a[i] = As[jj][ty * 4 + i];
#pragma unroll
            for (int k = 0; k < 3; k++) b[k] = Bs[jj][tx * 3 + k];
#pragma unroll
            for (int i = 0; i < 4; i++)
#pragma unroll
                for (int k = 0; k < 3; k++) acc[i][k] += a[i] * b[k];
        }
        __syncthreads();
    }

#pragma unroll
    for (int i = 0; i < 4; i++) {
        int t = t0 + ty * 4 + i;
#pragma unroll
        for (int k = 0; k < 3; k++) {
            int kk = tx * 3 + k;
            g_feats[t * K_TAGS + kk] = acc[i][k] + b_out[kk];
        }
    }
}

// ---------------- Viterbi + backtrace (96 threads, max-then-ffs argmax) ----------------
// Warp w, lane l: tag = w*16 + (l&15), half = l>>4 owns prev range
// [half*24, half*24+24). Per step: FMNMX tree (depth 5, 4 cyc/level) for the
// value max, then equality bitmask + __ffs for the FIRST matching index
// (bv is bit-identical to one of the s[j], so == is exact; lowest set bit =
// first index = jnp.argmax). Cross-half combine via shfl_xor(16), half1 wins
// only on strict >. One __syncthreads per step.
#define VIT_SMEM (T_LEN * K_TAGS + 2 * K_TAGS * 4 + 16)
extern __shared__ unsigned char vit_smem[];
__global__ void viterbi_kernel(const float* __restrict__ trans,
                               float* __restrict__ out) {
    unsigned char* bptr = vit_smem;                          // [T][48] u8 = 96KB
    float* fvs = (float*)(vit_smem + T_LEN * K_TAGS);        // [2][48], 16B aligned
    int tid = threadIdx.x;  // 96
    int l = tid & 31;
    int wid = tid >> 5;                    // 0..2
    int tag = wid * 16 + (l & 15);
    int half = l >> 4;                     // 0 or 1
    int jlo = half * 24;

    float tr[24];
#pragma unroll
    for (int j = 0; j < 24; j++) tr[j] = trans[tag * K_TAGS + jlo + j];
    if (half == 0) fvs[tag] = (tag == START_TAG) ? 0.f : -10000.f;
    float featp = (half == 0) ? g_feats[tag] : 0.f;
    __syncthreads();

    for (int t = 0; t < T_LEN; t++) {
        int cur = (t & 1) * K_TAGS;
        int nxt = K_TAGS - cur;

        // vectorized fv load + scores
        float s[24];
        {
            const float4* fp = (const float4*)&fvs[cur + jlo];
#pragma unroll
            for (int q = 0; q < 6; q++) {
                float4 f = fp[q];
                s[q * 4]     = f.x + tr[q * 4];
                s[q * 4 + 1] = f.y + tr[q * 4 + 1];
                s[q * 4 + 2] = f.z + tr[q * 4 + 2];
                s[q * 4 + 3] = f.w + tr[q * 4 + 3];
            }
        }

        // value max: FMNMX tree, depth 5
        float m12[12];
#pragma unroll
        for (int j = 0; j < 12; j++) m12[j] = fmaxf(s[j], s[j + 12]);
        float m6[6];
#pragma unroll
        for (int j = 0; j < 6; j++) m6[j] = fmaxf(m12[j], m12[j + 6]);
        float m3[3];
#pragma unroll
        for (int j = 0; j < 3; j++) m3[j] = fmaxf(m6[j], m6[j + 3]);
        float bv = fmaxf(fmaxf(m3[0], m3[1]), m3[2]);

        // first index equal to bv: bitmask + ffs (4-way ILP OR accumulation)
        unsigned ma = 0, mb = 0, mc = 0, md = 0;
#pragma unroll
        for (int j = 0; j < 24; j += 4) {
            ma |= (s[j]     == bv) ? (1u << j)       : 0u;
            mb |= (s[j + 1] == bv) ? (1u << (j + 1)) : 0u;
            mc |= (s[j + 2] == bv) ? (1u << (j + 2)) : 0u;
            md |= (s[j + 3] == bv) ? (1u << (j + 3)) : 0u;
        }
        int ba = __ffs(ma | mb | mc | md) - 1 + jlo;

        // cross-half combine inside the warp (half0 <-> half1 at xor 16)
        float ov = __shfl_xor_sync(0xffffffffu, bv, 16);
        int   oa = __shfl_xor_sync(0xffffffffu, ba, 16);
        if (half == 0) {
            // strict > : ties keep half0 (smaller prev indices) = jnp.argmax
            if (ov > bv) { bv = ov; ba = oa; }
            fvs[nxt + tag] = bv + featp;
            bptr[t * K_TAGS + tag] = (unsigned char)ba;
            if (t + 1 < T_LEN) featp = g_feats[(t + 1) * K_TAGS + tag];
        }
        __syncthreads();
    }

    if (tid == 0) {
        int cur = (T_LEN & 1) * K_TAGS;   // = 0 for even T
        float best = -3.4e38f;
        int btag = 0;
#pragma unroll
        for (int j = 0; j < K_TAGS; j++) {
            float sc = fvs[cur + j] + trans[STOP_TAG * K_TAGS + j];
            if (sc > best) { best = sc; btag = j; }
        }
        out[0] = best;
        for (int t = T_LEN - 1; t >= 0; t--) {
            out[1 + t] = (float)btag;
            btag = bptr[t * K_TAGS + btag];
        }
    }
}

// ---------------- launch ----------------
extern "C" void kernel_launch(void* const* d_in, const int* in_sizes, int n_in,
                              void* d_out, int out_size) {
    const int*   sent   = (const int*)d_in[0];
    const float* E      = (const float*)d_in[1];
    const float* W_ih_f = (const float*)d_in[2];
    const float* W_hh_f = (const float*)d_in[3];
    const float* b_ih_f = (const float*)d_in[4];
    const float* b_hh_f = (const float*)d_in[5];
    const float* W_ih_b = (const float*)d_in[6];
    const float* W_hh_b = (const float*)d_in[7];
    const float* b_ih_b = (const float*)d_in[8];
    const float* b_hh_b = (const float*)d_in[9];
    const float* W_out  = (const float*)d_in[10];
    const float* b_out  = (const float*)d_in[11];
    const float* trans  = (const float*)d_in[12];
    float* out = (float*)d_out;

    cudaFuncSetAttribute(viterbi_kernel,
                         cudaFuncAttributeMaxDynamicSharedMemorySize, VIT_SMEM);

    // gather + xg GEMM + both LSTM directions in ONE launch
    mega_kernel<<<dim3(8, 18, 1), 512>>>(sent, E,
                                         W_ih_f, W_hh_f, b_ih_f, b_hh_f,
                                         W_ih_b, W_hh_b, b_ih_b, b_hh_b);

    feats_gemm_kernel<<<T_LEN / FT_TT, 256>>>(W_out, b_out);

    viterbi_kernel<<<1, 96, VIT_SMEM>>>(trans, out);
}